// round 5
// baseline (speedup 1.0000x reference)
#include <cuda_runtime.h>

#define M_ROWS   2048
#define NDIM     128
#define NNF4     (NDIM * NDIM / 4)     // 4096 float4 per row per component
#define CHUNK_I  8                     // i-slices per task
#define CHUNKS   (NDIM / CHUNK_I)      // 16 tasks per row
#define NTASKS   (M_ROWS * CHUNKS)     // 32768 tasks of 8 KB each
#define THREADS  1024

// Device scratch (allocation-free rule: __device__ globals)
__device__ float2   g_part[NTASKS * 16];   // per-task 16 half-lane partials (4 MB)
__device__ unsigned g_ctr = 0;

// ---------------------------------------------------------------------------
// Rank-2 bilinear form: v_row = lam0 * w0^H (B_row^T e0) - lam1 * w1^H (B_row^T e1)
//   t0[j] = sum_i e0[i] * B[i,j],  B = re - i*im  (conj basis)
//   t0r += e0r*re + e0i*im ;  t0i += e0i*re - e0r*im   (same for e1)
// Streamed operand = 2 KB of eigenvectors -> no dense h, no big smem.
// ---------------------------------------------------------------------------
__global__ __launch_bounds__(THREADS, 1) void fused_kernel(
    const float* __restrict__ bre, const float* __restrict__ bim,
    const float* __restrict__ theta, const float* __restrict__ evl,
    float* __restrict__ out)
{
    __shared__ float4 epack[NDIM];    // {e0r,e0i,e1r,e1i}[i] — broadcast by i
    __shared__ float4 efin[NDIM];     // transposed for conflict-free lane reload
    __shared__ float  wred[THREADS / 32];
    __shared__ float  sc[6];
    __shared__ unsigned slast;

    const int tid  = threadIdx.x;
    const int lane = tid & 31;
    const int warp = tid >> 5;

    // ---------------- phase A: eigvectors (Gram-Schmidt) ----------------
    float th0 = 0.f, th1 = 0.f, th2 = 0.f, th3 = 0.f;
    if (tid < NDIM) {
        th0 = theta[tid];
        th1 = theta[NDIM + tid];
        th2 = theta[2 * NDIM + tid];
        th3 = theta[3 * NDIM + tid];
    }

    auto blockReduce = [&](float v, int slot) -> float {
        #pragma unroll
        for (int o = 16; o; o >>= 1) v += __shfl_xor_sync(0xffffffffu, v, o);
        if (lane == 0) wred[warp] = v;
        __syncthreads();
        if (tid == 0) {
            float s = 0.f;
            #pragma unroll
            for (int i = 0; i < THREADS / 32; i++) s += wred[i];
            sc[slot] = s;
        }
        __syncthreads();
        return sc[slot];
    };

    const float s0   = blockReduce(th0 * th0 + th1 * th1, 0);
    const float inv0 = rsqrtf(s0);
    const float a0 = th0 * inv0, b0 = th1 * inv0;           // evc0
    const float dr = blockReduce(a0 * th2 + b0 * th3, 1);   // Re vdot(evc0,c1)
    const float di = blockReduce(a0 * th3 - b0 * th2, 2);   // Im vdot(evc0,c1)
    const float c1r = th2 - (dr * a0 - di * b0);
    const float c1i = th3 - (dr * b0 + di * a0);
    const float s1   = blockReduce(c1r * c1r + c1i * c1i, 3);
    const float inv1 = rsqrtf(s1);

    if (tid < NDIM) {
        const float4 e = make_float4(a0, b0, c1r * inv1, c1i * inv1);
        epack[tid] = e;
        efin[(tid & 3) * 32 + (tid >> 2)] = e;   // efin[jj*32 + lane], j = 4*lane+jj
    }
    if (tid == 0) {
        const float l0 = log1pf(expf(evl[0]));
        const float l1 = log1pf(expf(evl[1]));
        const float nl = rsqrtf(l0 * l0 + l1 * l1);
        sc[4] = l0 * nl;                                     // lam0
        sc[5] = l1 * nl;                                     // lam1
    }
    __syncthreads();
    const float lam0 = sc[4], lam1 = sc[5];

    // ---------------- phase B: static-stride 8KB-task streaming ----------------
    const float4* br4 = (const float4*)bre;
    const float4* bi4 = (const float4*)bim;
    const int gw = blockIdx.x * (THREADS / 32) + warp;       // global warp id
    const int nw = gridDim.x * (THREADS / 32);               // total warps

    for (int t = gw; t < NTASKS; t += nw) {
        const int row = t >> 4;
        const int ib  = (t & (CHUNKS - 1)) * CHUNK_I;
        const float4* bp = br4 + (size_t)row * NNF4 + ib * (NDIM / 4) + lane;
        const float4* mp = bi4 + (size_t)row * NNF4 + ib * (NDIM / 4) + lane;

        float4 t0r = {0,0,0,0}, t0i = {0,0,0,0};
        float4 t1r = {0,0,0,0}, t1i = {0,0,0,0};

        #pragma unroll
        for (int k = 0; k < CHUNK_I; k++) {
            const float4 r = __ldcs(bp + k * (NDIM / 4));
            const float4 m = __ldcs(mp + k * (NDIM / 4));
            const float4 e = epack[ib + k];                  // broadcast LDS.128
            t0r.x += e.x*r.x + e.y*m.x;  t0i.x += e.y*r.x - e.x*m.x;
            t0r.y += e.x*r.y + e.y*m.y;  t0i.y += e.y*r.y - e.x*m.y;
            t0r.z += e.x*r.z + e.y*m.z;  t0i.z += e.y*r.z - e.x*m.z;
            t0r.w += e.x*r.w + e.y*m.w;  t0i.w += e.y*r.w - e.x*m.w;
            t1r.x += e.z*r.x + e.w*m.x;  t1i.x += e.w*r.x - e.z*m.x;
            t1r.y += e.z*r.y + e.w*m.y;  t1i.y += e.w*r.y - e.z*m.y;
            t1r.z += e.z*r.z + e.w*m.z;  t1i.z += e.w*r.z - e.z*m.z;
            t1r.w += e.z*r.w + e.w*m.w;  t1i.w += e.w*r.w - e.z*m.w;
        }

        // finalize: z = sum_j conj(e[j]) * t[j] over this lane's 4 j's
        float z0r = 0.f, z0i = 0.f, z1r = 0.f, z1i = 0.f;
        {
            const float4 e0 = efin[lane];        // jj=0 : j=4*lane
            const float4 e1 = efin[32 + lane];   // jj=1
            const float4 e2 = efin[64 + lane];   // jj=2
            const float4 e3 = efin[96 + lane];   // jj=3
            z0r += e0.x*t0r.x + e0.y*t0i.x;  z0i += e0.x*t0i.x - e0.y*t0r.x;
            z0r += e1.x*t0r.y + e1.y*t0i.y;  z0i += e1.x*t0i.y - e1.y*t0r.y;
            z0r += e2.x*t0r.z + e2.y*t0i.z;  z0i += e2.x*t0i.z - e2.y*t0r.z;
            z0r += e3.x*t0r.w + e3.y*t0i.w;  z0i += e3.x*t0i.w - e3.y*t0r.w;
            z1r += e0.z*t1r.x + e0.w*t1i.x;  z1i += e0.z*t1i.x - e0.w*t1r.x;
            z1r += e1.z*t1r.y + e1.w*t1i.y;  z1i += e1.z*t1i.y - e1.w*t1r.y;
            z1r += e2.z*t1r.z + e2.w*t1i.z;  z1i += e2.z*t1i.z - e2.w*t1r.z;
            z1r += e3.z*t1r.w + e3.w*t1i.w;  z1i += e3.z*t1i.w - e3.w*t1r.w;
        }
        float vr = lam0 * z0r - lam1 * z1r;
        float vi = lam0 * z0i - lam1 * z1i;

        // single shuffle: lanes 0-15 hold (lane)+(lane+16) partials
        vr += __shfl_xor_sync(0xffffffffu, vr, 16);
        vi += __shfl_xor_sync(0xffffffffu, vi, 16);
        if (lane < 16) g_part[(size_t)t * 16 + lane] = make_float2(vr, vi);
    }

    // ---------------- phase C: last block reduces ----------------
    __syncthreads();
    if (tid == 0) {
        __threadfence();
        const unsigned old = atomicAdd(&g_ctr, 1u);
        slast = (old == gridDim.x - 1) ? 1u : 0u;
        if (slast) g_ctr = 0;                                // reset for replay
    }
    __syncthreads();

    if (slast) {
        __threadfence();
        float acc = 0.f;
        for (int r = tid; r < M_ROWS; r += THREADS) {        // 2 rows per thread
            const float4* pp = (const float4*)(g_part + (size_t)r * 256);
            float vr = 0.f, vi = 0.f;
            #pragma unroll 8
            for (int k = 0; k < 128; k++) {                  // 256 float2 partials
                const float4 q = __ldcg(pp + k);
                vr += q.x + q.z;
                vi += q.y + q.w;
            }
            acc += vr * vr + vi * vi;
        }
        #pragma unroll
        for (int o = 16; o; o >>= 1) acc += __shfl_xor_sync(0xffffffffu, acc, o);
        if (lane == 0) wred[warp] = acc;
        __syncthreads();
        if (warp == 0) {
            float v = wred[lane];
            #pragma unroll
            for (int o = 16; o; o >>= 1) v += __shfl_xor_sync(0xffffffffu, v, o);
            if (lane == 0) out[0] = v;
        }
    }
}

// ---------------------------------------------------------------------------
extern "C" void kernel_launch(void* const* d_in, const int* in_sizes, int n_in,
                              void* d_out, int out_size) {
    const float* bre   = (const float*)d_in[0];
    const float* bim   = (const float*)d_in[1];
    const float* theta = (const float*)d_in[2];
    const float* evl   = (const float*)d_in[3];

    int sms = 148;
    cudaDeviceGetAttribute(&sms, cudaDevAttrMultiProcessorCount, 0);

    fused_kernel<<<sms, THREADS>>>(bre, bim, theta, evl, (float*)d_out);
}

// round 6
// speedup vs baseline: 3.4953x; 3.4953x over previous
#include <cuda_runtime.h>

#define M_ROWS   2048
#define NDIM     128
#define NN       (NDIM * NDIM)       // 16384 complex entries of matH
#define NV4      (NN / 4)            // 4096 float4 per row per component
#define TASK_F4  256                 // float4 per task per component (2 iters x 128)
#define TPR      16                  // tasks per row
#define NTASKS   (M_ROWS * TPR)      // 32768 tasks of 8 KB each
#define THREADS  1024
#define RBLOCKS  64                  // reduce kernel: 64 blocks x 32 warps = 2048 rows

// Device scratch (allocation-free rule: __device__ globals)
__device__ float2   g_part[NTASKS * 16];   // 16 half-lane partials per task (4 MB)
__device__ float    g_bsum[RBLOCKS];
__device__ unsigned g_ctr = 0;

// ---------------------------------------------------------------------------
// Kernel 1: build matH in smem (128 KB), then stream 256 MB of basis with
// 8 KB tasks. Boundary = ONE shuffle + one 8B store, so load pipelining
// survives task boundaries; 32768 tasks / 4864 warps -> 96% balance.
// ---------------------------------------------------------------------------
__global__ __launch_bounds__(THREADS, 1) void fused_kernel(
    const float* __restrict__ bre, const float* __restrict__ bim,
    const float* __restrict__ theta, const float* __restrict__ evl)
{
    extern __shared__ float sh[];             // 2 * NN floats = 128 KB
    float* hre = sh;
    float* him = sh + NN;

    __shared__ float e0r[NDIM], e0i[NDIM], e1r[NDIM], e1i[NDIM];
    __shared__ float wred[THREADS / 32];
    __shared__ float sc[6];

    const int tid  = threadIdx.x;
    const int lane = tid & 31;
    const int warp = tid >> 5;

    // ---------------- phase A: eigvectors + matH ----------------
    float th0 = 0.f, th1 = 0.f, th2 = 0.f, th3 = 0.f;
    if (tid < NDIM) {
        th0 = theta[tid];
        th1 = theta[NDIM + tid];
        th2 = theta[2 * NDIM + tid];
        th3 = theta[3 * NDIM + tid];
    }

    auto blockReduce = [&](float v, int slot) -> float {
        #pragma unroll
        for (int o = 16; o; o >>= 1) v += __shfl_xor_sync(0xffffffffu, v, o);
        if (lane == 0) wred[warp] = v;
        __syncthreads();
        if (tid == 0) {
            float s = 0.f;
            #pragma unroll
            for (int i = 0; i < THREADS / 32; i++) s += wred[i];
            sc[slot] = s;
        }
        __syncthreads();
        return sc[slot];
    };

    const float s0   = blockReduce(th0 * th0 + th1 * th1, 0);
    const float inv0 = rsqrtf(s0);
    const float a0 = th0 * inv0, b0 = th1 * inv0;           // evc0
    const float dr = blockReduce(a0 * th2 + b0 * th3, 1);   // Re vdot(evc0,c1)
    const float di = blockReduce(a0 * th3 - b0 * th2, 2);   // Im vdot(evc0,c1)
    const float c1r = th2 - (dr * a0 - di * b0);
    const float c1i = th3 - (dr * b0 + di * a0);
    const float s1   = blockReduce(c1r * c1r + c1i * c1i, 3);
    const float inv1 = rsqrtf(s1);

    if (tid < NDIM) {
        e0r[tid] = a0;         e0i[tid] = b0;
        e1r[tid] = c1r * inv1; e1i[tid] = c1i * inv1;
    }
    if (tid == 0) {
        const float l0 = log1pf(expf(evl[0]));
        const float l1 = log1pf(expf(evl[1]));
        const float nl = rsqrtf(l0 * l0 + l1 * l1);
        sc[4] = l0 * nl;                                     // lam0
        sc[5] = l1 * nl;                                     // lam1
    }
    __syncthreads();
    const float lam0 = sc[4], lam1 = sc[5];

    #pragma unroll
    for (int k = 0; k < NN / THREADS; k++) {
        const int c = tid + k * THREADS;                     // stride-1 writes
        const int i = c >> 7, j = c & (NDIM - 1);
        const float A0 = e0r[i], B0 = e0i[i], A1 = e1r[i], B1 = e1i[i];
        const float aj0 = e0r[j], bj0 = e0i[j], aj1 = e1r[j], bj1 = e1i[j];
        hre[c] = lam0 * (A0 * aj0 + B0 * bj0) - lam1 * (A1 * aj1 + B1 * bj1);
        him[c] = lam0 * (B0 * aj0 - A0 * bj0) - lam1 * (B1 * aj1 - A1 * bj1);
    }
    __syncthreads();

    // ---------------- phase B: 8KB-task streaming ----------------
    // v = (re - i*im) . (hre + i*him):
    //   vr += re*hre + im*him ;  vi += re*him - im*hre
    const float4* hre4 = (const float4*)hre;
    const float4* him4 = (const float4*)him;
    const int gw = blockIdx.x * (THREADS / 32) + warp;       // global warp id
    const int nw = gridDim.x * (THREADS / 32);               // total warps

    for (int t = gw; t < NTASKS; t += nw) {
        const int row = t >> 4;                              // 0..2047
        const int cb  = (t & (TPR - 1)) * TASK_F4;           // float4 offset in row
        const int hb  = cb + lane;
        const float4* br = (const float4*)bre + (size_t)row * NV4 + cb + lane;
        const float4* bi = (const float4*)bim + (size_t)row * NV4 + cb + lane;

        float vr = 0.f, vi = 0.f;
        #pragma unroll 1
        for (int it = 0; it < 2; it++) {                     // 2 x 128 float4
            const int c = it * 128;
            const float4 r0 = __ldcs(br + c);
            const float4 r1 = __ldcs(br + c + 32);
            const float4 r2 = __ldcs(br + c + 64);
            const float4 r3 = __ldcs(br + c + 96);
            const float4 m0 = __ldcs(bi + c);
            const float4 m1 = __ldcs(bi + c + 32);
            const float4 m2 = __ldcs(bi + c + 64);
            const float4 m3 = __ldcs(bi + c + 96);

            float4 h, g;
            h = hre4[hb + c];      g = him4[hb + c];
            vr += r0.x*h.x + m0.x*g.x;  vi += r0.x*g.x - m0.x*h.x;
            vr += r0.y*h.y + m0.y*g.y;  vi += r0.y*g.y - m0.y*h.y;
            vr += r0.z*h.z + m0.z*g.z;  vi += r0.z*g.z - m0.z*h.z;
            vr += r0.w*h.w + m0.w*g.w;  vi += r0.w*g.w - m0.w*h.w;
            h = hre4[hb + c + 32]; g = him4[hb + c + 32];
            vr += r1.x*h.x + m1.x*g.x;  vi += r1.x*g.x - m1.x*h.x;
            vr += r1.y*h.y + m1.y*g.y;  vi += r1.y*g.y - m1.y*h.y;
            vr += r1.z*h.z + m1.z*g.z;  vi += r1.z*g.z - m1.z*h.z;
            vr += r1.w*h.w + m1.w*g.w;  vi += r1.w*g.w - m1.w*h.w;
            h = hre4[hb + c + 64]; g = him4[hb + c + 64];
            vr += r2.x*h.x + m2.x*g.x;  vi += r2.x*g.x - m2.x*h.x;
            vr += r2.y*h.y + m2.y*g.y;  vi += r2.y*g.y - m2.y*h.y;
            vr += r2.z*h.z + m2.z*g.z;  vi += r2.z*g.z - m2.z*h.z;
            vr += r2.w*h.w + m2.w*g.w;  vi += r2.w*g.w - m2.w*h.w;
            h = hre4[hb + c + 96]; g = him4[hb + c + 96];
            vr += r3.x*h.x + m3.x*g.x;  vi += r3.x*g.x - m3.x*h.x;
            vr += r3.y*h.y + m3.y*g.y;  vi += r3.y*g.y - m3.y*h.y;
            vr += r3.z*h.z + m3.z*g.z;  vi += r3.z*g.z - m3.z*h.z;
            vr += r3.w*h.w + m3.w*g.w;  vi += r3.w*g.w - m3.w*h.w;
        }
        // boundary: ONE shuffle, half-warp 8B stores (128B coalesced)
        vr += __shfl_xor_sync(0xffffffffu, vr, 16);
        vi += __shfl_xor_sync(0xffffffffu, vi, 16);
        if (lane < 16) g_part[(size_t)t * 16 + lane] = make_float2(vr, vi);
    }
}

// ---------------------------------------------------------------------------
// Kernel 2: warp-per-row reduction of the 4 MB partial array, then a
// deterministic last-block scalar reduce (counter self-resets for replay).
// ---------------------------------------------------------------------------
__global__ __launch_bounds__(THREADS) void reduce_kernel(float* __restrict__ out) {
    __shared__ float wred[THREADS / 32];
    __shared__ unsigned slast;

    const int tid  = threadIdx.x;
    const int lane = tid & 31;
    const int warp = tid >> 5;
    const int row  = blockIdx.x * (THREADS / 32) + warp;     // 64*32 = 2048 rows

    // 256 float2 partials per row = 128 float4, read as 4 per lane
    const float4* pp = (const float4*)(g_part + (size_t)row * 256);
    float vr = 0.f, vi = 0.f;
    #pragma unroll
    for (int k = 0; k < 4; k++) {
        const float4 q = __ldcg(pp + lane + k * 32);
        vr += q.x + q.z;
        vi += q.y + q.w;
    }
    #pragma unroll
    for (int o = 16; o; o >>= 1) {
        vr += __shfl_xor_sync(0xffffffffu, vr, o);
        vi += __shfl_xor_sync(0xffffffffu, vi, o);
    }
    if (lane == 0) wred[warp] = vr * vr + vi * vi;
    __syncthreads();

    if (tid == 0) {
        float s = 0.f;
        #pragma unroll
        for (int i = 0; i < THREADS / 32; i++) s += wred[i];
        g_bsum[blockIdx.x] = s;
        __threadfence();
        const unsigned old = atomicAdd(&g_ctr, 1u);
        slast = (old == gridDim.x - 1) ? 1u : 0u;
        if (slast) g_ctr = 0;                                // reset for replay
    }
    __syncthreads();

    if (slast && warp == 0) {
        float v = (lane < RBLOCKS) ? __ldcg(&g_bsum[lane]) : 0.f;
        if (lane + 32 < RBLOCKS) v += __ldcg(&g_bsum[lane + 32]);
        #pragma unroll
        for (int o = 16; o; o >>= 1) v += __shfl_xor_sync(0xffffffffu, v, o);
        if (lane == 0) out[0] = v;
    }
}

// ---------------------------------------------------------------------------
extern "C" void kernel_launch(void* const* d_in, const int* in_sizes, int n_in,
                              void* d_out, int out_size) {
    const float* bre   = (const float*)d_in[0];
    const float* bim   = (const float*)d_in[1];
    const float* theta = (const float*)d_in[2];
    const float* evl   = (const float*)d_in[3];

    int sms = 148;
    cudaDeviceGetAttribute(&sms, cudaDevAttrMultiProcessorCount, 0);

    const int smem = 2 * NN * (int)sizeof(float);            // 128 KB
    cudaFuncSetAttribute(fused_kernel, cudaFuncAttributeMaxDynamicSharedMemorySize, smem);

    fused_kernel<<<sms, THREADS, smem>>>(bre, bim, theta, evl);
    reduce_kernel<<<RBLOCKS, THREADS>>>((float*)d_out);
}